// round 7
// baseline (speedup 1.0000x reference)
#include <cuda_runtime.h>
#include <cuda_bf16.h>
#include <cstdint>
#include <cstddef>

#define NQ   65536
#define MS   65536
#define HN   32
#define CIN  64
#define CO   64
#define KP   15
#define KTOT 960            // KP * CIN

// ---- device scratch ----------------------------------------------------------
__device__ __nv_bfloat16 g_wth[(size_t)NQ * KTOT];   // weighted, bf16 hi
__device__ __nv_bfloat16 g_wtl[(size_t)NQ * KTOT];   // weighted, bf16 lo
__device__ __nv_bfloat16 g_Wth[(size_t)CO * KTOT];   // W^T [o][k*64+i], bf16 hi
__device__ __nv_bfloat16 g_Wtl[(size_t)CO * KTOT];   // W^T, bf16 lo
__device__ __nv_bfloat16 g_xh[(size_t)MS * CIN];     // x, bf16 hi
__device__ __nv_bfloat16 g_xl[(size_t)MS * CIN];     // x, bf16 lo

__device__ float g_sums[CO];
__device__ float g_sumsq[CO];
__device__ float g_scale[CO];
__device__ float g_bias[CO];

// ---- helpers -------------------------------------------------------------------
static __device__ __forceinline__ float fast_sqrt(float x) {
    float r;
    asm("sqrt.approx.f32 %0, %1;" : "=f"(r) : "f"(x));
    return r;
}
static __device__ __forceinline__ void cp_async16(uint32_t smem_dst, const void* gmem_src) {
    asm volatile("cp.async.cg.shared.global [%0], [%1], 16;"
                 :: "r"(smem_dst), "l"(gmem_src));
}
static __device__ __forceinline__ void cp_commit() { asm volatile("cp.async.commit_group;"); }
static __device__ __forceinline__ void cp_wait0()  { asm volatile("cp.async.wait_group 0;"); }
static __device__ __forceinline__ void cp_wait1()  { asm volatile("cp.async.wait_group 1;"); }

static __device__ __forceinline__ uint32_t smem_u32(const void* p) {
    uint32_t a;
    asm("{ .reg .u64 t; cvta.to.shared.u64 t, %1; cvt.u32.u64 %0, t; }" : "=r"(a) : "l"(p));
    return a;
}

#define SWZ128(b)   ((b) ^ (((b) >> 3) & 0x70))

#define LDSM4(r0, r1, r2, r3, addr) \
    asm volatile("ldmatrix.sync.aligned.m8n8.x4.shared.b16 {%0,%1,%2,%3}, [%4];" \
        : "=r"(r0), "=r"(r1), "=r"(r2), "=r"(r3) : "r"(addr))

#define LDSM4T(r0, r1, r2, r3, addr) \
    asm volatile("ldmatrix.sync.aligned.m8n8.x4.trans.shared.b16 {%0,%1,%2,%3}, [%4];" \
        : "=r"(r0), "=r"(r1), "=r"(r2), "=r"(r3) : "r"(addr))

#define MMA16816(c, a0, a1, a2, a3, b0, b1) \
    asm volatile("mma.sync.aligned.m16n8k16.row.col.f32.bf16.bf16.f32 " \
        "{%0,%1,%2,%3}, {%4,%5,%6,%7}, {%8,%9}, {%0,%1,%2,%3};" \
        : "+f"((c)[0]), "+f"((c)[1]), "+f"((c)[2]), "+f"((c)[3]) \
        : "r"(a0), "r"(a1), "r"(a2), "r"(a3), "r"(b0), "r"(b1))

// =============================================================================
// Kernel P1: split x -> bf16 hi/lo
// =============================================================================
__global__ void __launch_bounds__(256)
prep_x(const float* __restrict__ x) {
    const int i = blockIdx.x * 256 + threadIdx.x;
    float v = x[i];
    __nv_bfloat16 hi = __float2bfloat16(v);
    __nv_bfloat16 lo = __float2bfloat16(v - __bfloat162float(hi));
    g_xh[i] = hi;
    g_xl[i] = lo;
}

// =============================================================================
// Kernel P2: split/transpose W -> Wt[o][k*64+i] bf16 hi/lo
// =============================================================================
__global__ void __launch_bounds__(64)
prep_w(const float* __restrict__ Wg) {
    const int ki = blockIdx.x;              // 0..959
    const int o  = threadIdx.x;             // 0..63
    float w = Wg[ki * 64 + o];
    __nv_bfloat16 hi = __float2bfloat16(w);
    __nv_bfloat16 lo = __float2bfloat16(w - __bfloat162float(hi));
    g_Wth[(size_t)o * KTOT + ki] = hi;
    g_Wtl[(size_t)o * KTOT + ki] = lo;
}

// =============================================================================
// Kernel A: HMMA aggregation, SOFTWARE-PIPELINED.
//   Warp processes QW queries; gather(q+1) overlaps influence+MMA(q).
//   Per-warp SMEM: x double buffer 2x8KB (SW128) + infl hi/lo 2x1280B (80B rows)
// =============================================================================
#define QW       8
#define AW_SIZE  18944                       // per-warp smem bytes
#define AW_XB(b) ((b) * 8192u)               // x buffer b: hi at +0, lo at +4096
#define AW_IH    16384u
#define AW_IL    17664u
#define AGG_SMEM (4 * AW_SIZE)               // 75776 bytes

__global__ void __launch_bounds__(128)
kpconv_aggregate_tc(const float* __restrict__ q_pts,
                    const float* __restrict__ s_pts,
                    const int*   __restrict__ nbr,
                    const float* __restrict__ kp)
{
    extern __shared__ char smA[];
    __shared__ float4 kp4s[16];

    const int tid  = threadIdx.x;
    const int warp = tid >> 5;
    const int lane = tid & 31;
    const uint32_t wb = smem_u32(smA) + warp * AW_SIZE;

    if (blockIdx.x == 0 && tid < CO) { g_sums[tid] = 0.f; g_sumsq[tid] = 0.f; }

    if (tid < 16) {
        float4 v = make_float4(0.f, 0.f, 0.f, 0.f);
        if (tid < KP) {
            v.x = kp[tid * 3 + 0];
            v.y = kp[tid * 3 + 1];
            v.z = kp[tid * 3 + 2];
        }
        kp4s[tid] = v;
    }
    __syncthreads();

    const double EXT_D = 0.1 * 1.2 / 2.5;
    const float  INV_E = (float)(1.0 / EXT_D);

    const int q0 = (blockIdx.x * 4 + warp) * QW;

    // MMA lane-mapping constants (validated in R6)
    const int krow_base = (lane & 7) + ((lane >> 3) & 1) * 8;
    const uint32_t a_off = (uint32_t)((lane & 15) * 80 + (lane >> 4) * 16);
    const int kp0 = lane >> 2;
    const int kp1 = kp0 + 8;
    const int cb  = 2 * (lane & 3);

    // ---- prologue: gather for q0 into buffer 0 ----
    int idx_cur = nbr[q0 * HN + lane];
    #pragma unroll
    for (int i = 0; i < 8; ++i) {
        const int v = i * 32 + lane;
        const int r = v >> 3, u = v & 7;
        const int ir = __shfl_sync(0xffffffffu, idx_cur, r);
        const uint32_t d = SWZ128((uint32_t)(r * 128 + u * 16));
        cp_async16(wb + AW_XB(0) + d,        g_xh + (size_t)ir * CIN + u * 8);
        cp_async16(wb + AW_XB(0) + 4096 + d, g_xl + (size_t)ir * CIN + u * 8);
    }
    cp_commit();

    #pragma unroll 1
    for (int qi = 0; qi < QW; ++qi) {
        const int q = q0 + qi;

        // ---- issue gather for q+1 (overlaps everything below) ----
        int idx_next = 0;
        if (qi + 1 < QW) {
            idx_next = nbr[(q + 1) * HN + lane];
            const uint32_t xb = wb + AW_XB((qi + 1) & 1);
            #pragma unroll
            for (int i = 0; i < 8; ++i) {
                const int v = i * 32 + lane;
                const int r = v >> 3, u = v & 7;
                const int ir = __shfl_sync(0xffffffffu, idx_next, r);
                const uint32_t d = SWZ128((uint32_t)(r * 128 + u * 16));
                cp_async16(xb + d,        g_xh + (size_t)ir * CIN + u * 8);
                cp_async16(xb + 4096 + d, g_xl + (size_t)ir * CIN + u * 8);
            }
            cp_commit();
        }

        // ---- influence for q (lane = neighbor) ----
        const float qx = q_pts[q * 3 + 0];
        const float qy = q_pts[q * 3 + 1];
        const float qz = q_pts[q * 3 + 2];
        const float rx = s_pts[idx_cur * 3 + 0] - qx;
        const float ry = s_pts[idx_cur * 3 + 1] - qy;
        const float rz = s_pts[idx_cur * 3 + 2] - qz;

        #pragma unroll
        for (int k = 0; k < 16; ++k) {
            float w = 0.f;
            if (k < KP) {
                float4 kv = kp4s[k];
                float dx = rx - kv.x, dy = ry - kv.y, dz = rz - kv.z;
                float d2 = fmaf(dx, dx, fmaf(dy, dy, dz * dz));
                float s  = fast_sqrt(d2);
                w = fmaxf(fmaf(s, -INV_E, 1.f), 0.f);
            }
            __nv_bfloat16 h = __float2bfloat16(w);
            __nv_bfloat16 l = __float2bfloat16(w - __bfloat162float(h));
            asm volatile("st.shared.b16 [%0], %1;" :: "r"(wb + AW_IH + k * 80 + lane * 2),
                         "h"(*(unsigned short*)&h) : "memory");
            asm volatile("st.shared.b16 [%0], %1;" :: "r"(wb + AW_IL + k * 80 + lane * 2),
                         "h"(*(unsigned short*)&l) : "memory");
        }
        __syncwarp();

        // ---- wait for q's gather (keep q+1's group in flight) ----
        if (qi + 1 < QW) cp_wait1(); else cp_wait0();
        __syncwarp();

        // ---- MMAs ----
        const uint32_t xh = wb + AW_XB(qi & 1);
        const uint32_t xl = xh + 4096;

        float acc[8][4];
        #pragma unroll
        for (int t = 0; t < 8; ++t)
            #pragma unroll
            for (int e = 0; e < 4; ++e) acc[t][e] = 0.f;

        #pragma unroll
        for (int s = 0; s < 2; ++s) {
            uint32_t ah0, ah1, ah2, ah3, al0, al1, al2, al3;
            LDSM4(ah0, ah1, ah2, ah3, wb + AW_IH + a_off + s * 32);
            LDSM4(al0, al1, al2, al3, wb + AW_IL + a_off + s * 32);

            const int krow = s * 16 + krow_base;
            #pragma unroll
            for (int t = 0; t < 4; ++t) {
                const uint32_t boff =
                    SWZ128((uint32_t)(krow * 128 + t * 32 + ((lane >> 4) * 16)));
                uint32_t bh0, bh1, bh2, bh3, bl0, bl1, bl2, bl3;
                LDSM4T(bh0, bh1, bh2, bh3, xh + boff);
                LDSM4T(bl0, bl1, bl2, bl3, xl + boff);

                MMA16816(acc[2 * t],     ah0, ah1, ah2, ah3, bh0, bh1);
                MMA16816(acc[2 * t],     ah0, ah1, ah2, ah3, bl0, bl1);
                MMA16816(acc[2 * t],     al0, al1, al2, al3, bh0, bh1);
                MMA16816(acc[2 * t + 1], ah0, ah1, ah2, ah3, bh2, bh3);
                MMA16816(acc[2 * t + 1], ah0, ah1, ah2, ah3, bl2, bl3);
                MMA16816(acc[2 * t + 1], al0, al1, al2, al3, bh2, bh3);
            }
        }
        __syncwarp();

        // ---- epilogue: split weighted -> bf16 hi/lo, write ----
        __nv_bfloat16* dh = g_wth + (size_t)q * KTOT;
        __nv_bfloat16* dl = g_wtl + (size_t)q * KTOT;
        #pragma unroll
        for (int t = 0; t < 8; ++t) {
            const int c = t * 8 + cb;
            {
                float v0 = acc[t][0], v1 = acc[t][1];
                __nv_bfloat16 h0 = __float2bfloat16(v0);
                __nv_bfloat16 h1 = __float2bfloat16(v1);
                __nv_bfloat16 l0 = __float2bfloat16(v0 - __bfloat162float(h0));
                __nv_bfloat16 l1 = __float2bfloat16(v1 - __bfloat162float(h1));
                *(__nv_bfloat162*)(dh + kp0 * 64 + c) = __nv_bfloat162(h0, h1);
                *(__nv_bfloat162*)(dl + kp0 * 64 + c) = __nv_bfloat162(l0, l1);
            }
            if (kp1 < KP) {
                float v0 = acc[t][2], v1 = acc[t][3];
                __nv_bfloat16 h0 = __float2bfloat16(v0);
                __nv_bfloat16 h1 = __float2bfloat16(v1);
                __nv_bfloat16 l0 = __float2bfloat16(v0 - __bfloat162float(h0));
                __nv_bfloat16 l1 = __float2bfloat16(v1 - __bfloat162float(h1));
                *(__nv_bfloat162*)(dh + kp1 * 64 + c) = __nv_bfloat162(h0, h1);
                *(__nv_bfloat162*)(dl + kp1 * 64 + c) = __nv_bfloat162(l0, l1);
            }
        }

        idx_cur = idx_next;
    }
}

// =============================================================================
// Kernel B: HMMA GEMM  out[128-tile][64] = weighted x W^T  (3-term bf16)
//   + fused BN partial sums   (unchanged from R6: measured 110us, correct)
// =============================================================================
#define HB_AH(b) ((b) * 49152u + 0u)
#define HB_AL(b) ((b) * 49152u + 16384u)
#define HB_WH(b) ((b) * 49152u + 32768u)
#define HB_WL(b) ((b) * 49152u + 40960u)
#define HB_RED   98304u
#define HB_TOTAL (98304 + 512)

extern __shared__ char smH[];

static __device__ __forceinline__ void load_chunk(uint32_t sb, int buf, int qbase, int c,
                                                  int tid) {
    #pragma unroll
    for (int i = 0; i < 4; ++i) {
        const int v = i * 256 + tid;
        const int row = v >> 3, u = v & 7;
        const uint32_t d = SWZ128((uint32_t)(row * 128 + u * 16));
        const size_t so = (size_t)(qbase + row) * KTOT + c * 64 + u * 8;
        cp_async16(sb + HB_AH(buf) + d, g_wth + so);
        cp_async16(sb + HB_AL(buf) + d, g_wtl + so);
    }
    #pragma unroll
    for (int i = 0; i < 2; ++i) {
        const int v = i * 256 + tid;
        const int row = v >> 3, u = v & 7;
        const uint32_t d = SWZ128((uint32_t)(row * 128 + u * 16));
        const size_t so = (size_t)row * KTOT + c * 64 + u * 8;
        cp_async16(sb + HB_WH(buf) + d, g_Wth + so);
        cp_async16(sb + HB_WL(buf) + d, g_Wtl + so);
    }
    cp_commit();
}

__global__ void __launch_bounds__(256, 2)
kpconv_gemm_hmma(float* __restrict__ out)
{
    const uint32_t sb = smem_u32(smH);
    const int tid   = threadIdx.x;
    const int warp  = tid >> 5;
    const int lane  = tid & 31;
    const int qbase = blockIdx.x * 128;

    float* red  = (float*)(smH + HB_RED);
    float* red2 = red + 64;
    if (tid < 128) red[tid] = 0.f;

    const int a_row = warp * 16 + (lane & 15);
    const int a_cb  = (lane >> 4) * 16;
    const int b_row = (lane & 7) + ((lane >> 4) << 3);
    const int b_cb  = ((lane >> 3) & 1) * 16;

    float acc[8][4];
    #pragma unroll
    for (int t = 0; t < 8; ++t)
        #pragma unroll
        for (int e = 0; e < 4; ++e) acc[t][e] = 0.f;

    load_chunk(sb, 0, qbase, 0, tid);
    load_chunk(sb, 1, qbase, 1, tid);

    #pragma unroll 1
    for (int c = 0; c < 15; ++c) {
        const int buf = c & 1;
        if (c < 14) cp_wait1(); else cp_wait0();
        __syncthreads();

        const uint32_t ahb = sb + HB_AH(buf);
        const uint32_t alb = sb + HB_AL(buf);
        const uint32_t whb = sb + HB_WH(buf);
        const uint32_t wlb = sb + HB_WL(buf);

        #pragma unroll
        for (int s = 0; s < 4; ++s) {
            const uint32_t aoff = SWZ128((uint32_t)(a_row * 128 + s * 32 + a_cb));
            uint32_t ah0, ah1, ah2, ah3, al0, al1, al2, al3;
            LDSM4(ah0, ah1, ah2, ah3, ahb + aoff);
            LDSM4(al0, al1, al2, al3, alb + aoff);

            #pragma unroll
            for (int p = 0; p < 4; ++p) {
                const uint32_t boff =
                    SWZ128((uint32_t)((p * 16 + b_row) * 128 + s * 32 + b_cb));
                uint32_t bh0, bh1, bh2, bh3, bl0, bl1, bl2, bl3;
                LDSM4(bh0, bh1, bh2, bh3, whb + boff);
                LDSM4(bl0, bl1, bl2, bl3, wlb + boff);

                MMA16816(acc[2 * p],     ah0, ah1, ah2, ah3, bh0, bh1);
                MMA16816(acc[2 * p],     ah0, ah1, ah2, ah3, bl0, bl1);
                MMA16816(acc[2 * p],     al0, al1, al2, al3, bh0, bh1);
                MMA16816(acc[2 * p + 1], ah0, ah1, ah2, ah3, bh2, bh3);
                MMA16816(acc[2 * p + 1], ah0, ah1, ah2, ah3, bl2, bl3);
                MMA16816(acc[2 * p + 1], al0, al1, al2, al3, bh2, bh3);
            }
        }

        __syncthreads();
        if (c + 2 < 15) load_chunk(sb, buf, qbase, c + 2, tid);
    }

    const int tm = lane >> 2;
    const int tn = (lane & 3) * 2;
    const int n0 = qbase + warp * 16 + tm;
    #pragma unroll
    for (int t = 0; t < 8; ++t) {
        const int col = t * 8 + tn;
        *(float2*)(out + (size_t)n0 * CO + col)       = make_float2(acc[t][0], acc[t][1]);
        *(float2*)(out + (size_t)(n0 + 8) * CO + col) = make_float2(acc[t][2], acc[t][3]);
        atomicAdd(red  + col,     acc[t][0] + acc[t][2]);
        atomicAdd(red  + col + 1, acc[t][1] + acc[t][3]);
        atomicAdd(red2 + col,     fmaf(acc[t][0], acc[t][0], acc[t][2] * acc[t][2]));
        atomicAdd(red2 + col + 1, fmaf(acc[t][1], acc[t][1], acc[t][3] * acc[t][3]));
    }
    __syncthreads();
    if (tid < 64)       atomicAdd(&g_sums[tid], red[tid]);
    else if (tid < 128) atomicAdd(&g_sumsq[tid - 64], red2[tid - 64]);
}

// =============================================================================
__global__ void finalize_stats_kernel(const float* __restrict__ gamma,
                                      const float* __restrict__ beta) {
    int o = threadIdx.x;
    if (o < CO) {
        const float invN = 1.f / (float)NQ;
        float mean = g_sums[o] * invN;
        float var  = g_sumsq[o] * invN - mean * mean;
        float inv  = rsqrtf(var + 1e-5f);
        float sc   = gamma[o] * inv;
        g_scale[o] = sc;
        g_bias[o]  = fmaf(-mean, sc, beta[o]);
    }
}

__global__ void __launch_bounds__(256)
bn_act_kernel(float* __restrict__ out) {
    const int i = blockIdx.x * 256 + threadIdx.x;
    float4 v = ((const float4*)out)[i];
    const int c = (i & 15) * 4;
    float r0 = fmaf(v.x, g_scale[c + 0], g_bias[c + 0]);
    float r1 = fmaf(v.y, g_scale[c + 1], g_bias[c + 1]);
    float r2 = fmaf(v.z, g_scale[c + 2], g_bias[c + 2]);
    float r3 = fmaf(v.w, g_scale[c + 3], g_bias[c + 3]);
    r0 = (r0 >= 0.f) ? r0 : 0.1f * r0;
    r1 = (r1 >= 0.f) ? r1 : 0.1f * r1;
    r2 = (r2 >= 0.f) ? r2 : 0.1f * r2;
    r3 = (r3 >= 0.f) ? r3 : 0.1f * r3;
    ((float4*)out)[i] = make_float4(r0, r1, r2, r3);
}

// =============================================================================
extern "C" void kernel_launch(void* const* d_in, const int* in_sizes, int n_in,
                              void* d_out, int out_size) {
    const float* x      = (const float*)d_in[0];
    const float* q_pts  = (const float*)d_in[1];
    const float* s_pts  = (const float*)d_in[2];
    const int*   nbr    = (const int*)d_in[3];
    const float* kp     = (const float*)d_in[4];
    const float* Wg     = (const float*)d_in[5];
    const float* gamma  = (const float*)d_in[6];
    const float* beta   = (const float*)d_in[7];
    float*       out    = (float*)d_out;

    cudaFuncSetAttribute(kpconv_aggregate_tc,
                         cudaFuncAttributeMaxDynamicSharedMemorySize, AGG_SMEM);
    cudaFuncSetAttribute(kpconv_gemm_hmma,
                         cudaFuncAttributeMaxDynamicSharedMemorySize, HB_TOTAL);

    prep_x<<<(MS * CIN) / 256, 256>>>(x);
    prep_w<<<KTOT, 64>>>(Wg);
    kpconv_aggregate_tc<<<NQ / (4 * QW), 128, AGG_SMEM>>>(q_pts, s_pts, nbr, kp);
    kpconv_gemm_hmma<<<NQ / 128, 256, HB_TOTAL>>>(out);
    finalize_stats_kernel<<<1, 64>>>(gamma, beta);
    bn_act_kernel<<<(NQ * CO / 4) / 256, 256>>>(out);
}

// round 8
// speedup vs baseline: 1.1043x; 1.1043x over previous
#include <cuda_runtime.h>
#include <cuda_bf16.h>
#include <cstdint>
#include <cstddef>

#define NQ   65536
#define MS   65536
#define HN   32
#define CIN  64
#define CO   64
#define KP   15
#define KTOT 960            // KP * CIN

// ---- device scratch ----------------------------------------------------------
__device__ __nv_bfloat16 g_wth[(size_t)NQ * KTOT];   // weighted, bf16 hi
__device__ __nv_bfloat16 g_wtl[(size_t)NQ * KTOT];   // weighted, bf16 lo
__device__ __nv_bfloat16 g_Wth[(size_t)CO * KTOT];   // W^T [o][k*64+i], bf16 hi
__device__ __nv_bfloat16 g_Wtl[(size_t)CO * KTOT];   // W^T, bf16 lo

__device__ float g_sums[CO];
__device__ float g_sumsq[CO];
__device__ float g_scale[CO];
__device__ float g_bias[CO];

// ---- fp32x2 helpers ------------------------------------------------------------
static __device__ __forceinline__ unsigned long long pk2(float lo, float hi) {
    unsigned long long r;
    asm("mov.b64 %0, {%1, %2};" : "=l"(r) : "f"(lo), "f"(hi));
    return r;
}
static __device__ __forceinline__ void upk2(unsigned long long v, float &lo, float &hi) {
    asm("mov.b64 {%0, %1}, %2;" : "=f"(lo), "=f"(hi) : "l"(v));
}
static __device__ __forceinline__ unsigned long long ffma2(unsigned long long a,
                                                           unsigned long long b,
                                                           unsigned long long c) {
    unsigned long long d;
    asm("fma.rn.f32x2 %0, %1, %2, %3;" : "=l"(d) : "l"(a), "l"(b), "l"(c));
    return d;
}
static __device__ __forceinline__ float fast_sqrt(float x) {
    float r;
    asm("sqrt.approx.f32 %0, %1;" : "=f"(r) : "f"(x));
    return r;
}

// ---- cp.async -------------------------------------------------------------------
static __device__ __forceinline__ void cp_async16(uint32_t smem_dst, const void* gmem_src) {
    asm volatile("cp.async.cg.shared.global [%0], [%1], 16;"
                 :: "r"(smem_dst), "l"(gmem_src));
}
static __device__ __forceinline__ void cp_commit() { asm volatile("cp.async.commit_group;"); }
static __device__ __forceinline__ void cp_wait0()  { asm volatile("cp.async.wait_group 0;"); }
static __device__ __forceinline__ void cp_wait1()  { asm volatile("cp.async.wait_group 1;"); }

static __device__ __forceinline__ uint32_t smem_u32(const void* p) {
    uint32_t a;
    asm("{ .reg .u64 t; cvta.to.shared.u64 t, %1; cvt.u32.u64 %0, t; }" : "=r"(a) : "l"(p));
    return a;
}

#define SWZ64(b)    ((b) ^ (((b) >> 3) & 0x30))

#define LDSM4(r0, r1, r2, r3, addr) \
    asm volatile("ldmatrix.sync.aligned.m8n8.x4.shared.b16 {%0,%1,%2,%3}, [%4];" \
        : "=r"(r0), "=r"(r1), "=r"(r2), "=r"(r3) : "r"(addr))

#define MMA16816(c, a0, a1, a2, a3, b0, b1) \
    asm volatile("mma.sync.aligned.m16n8k16.row.col.f32.bf16.bf16.f32 " \
        "{%0,%1,%2,%3}, {%4,%5,%6,%7}, {%8,%9}, {%0,%1,%2,%3};" \
        : "+f"((c)[0]), "+f"((c)[1]), "+f"((c)[2]), "+f"((c)[3]) \
        : "r"(a0), "r"(a1), "r"(a2), "r"(a3), "r"(b0), "r"(b1))

// =============================================================================
// Kernel P: split/transpose W -> Wt[o][k*64+i] bf16 hi/lo
// =============================================================================
__global__ void __launch_bounds__(64)
prep_w(const float* __restrict__ Wg) {
    const int ki = blockIdx.x;              // 0..959
    const int o  = threadIdx.x;             // 0..63
    float w = Wg[ki * 64 + o];
    __nv_bfloat16 hi = __float2bfloat16(w);
    __nv_bfloat16 lo = __float2bfloat16(w - __bfloat162float(hi));
    g_Wth[(size_t)o * KTOT + ki] = hi;
    g_Wtl[(size_t)o * KTOT + ki] = lo;
}

// =============================================================================
// Kernel A: FFMA2 aggregation (R5 version — measured fastest)
//   warp per query; writes weighted bf16 hi/lo; block 0 zeroes BN accumulators
// =============================================================================
__global__ void __launch_bounds__(256)
kpconv_aggregate(const float* __restrict__ x,
                 const float* __restrict__ q_pts,
                 const float* __restrict__ s_pts,
                 const int*   __restrict__ nbr,
                 const float* __restrict__ kp)
{
    __shared__ float4 ws4[8][32][4];
    __shared__ float4 kp4s[16];

    const int tid  = threadIdx.x;
    const int warp = tid >> 5;
    const int lane = tid & 31;

    if (blockIdx.x == 0 && tid < CO) { g_sums[tid] = 0.f; g_sumsq[tid] = 0.f; }

    if (tid < 16) {
        float4 v = make_float4(0.f, 0.f, 0.f, 0.f);
        if (tid < KP) {
            v.x = kp[tid * 3 + 0];
            v.y = kp[tid * 3 + 1];
            v.z = kp[tid * 3 + 2];
        }
        kp4s[tid] = v;
    }
    __syncthreads();

    const double EXT_D = 0.1 * 1.2 / 2.5;
    const float  INV_E = (float)(1.0 / EXT_D);

    const int q = blockIdx.x * 8 + warp;

    const float qx = q_pts[q * 3 + 0];
    const float qy = q_pts[q * 3 + 1];
    const float qz = q_pts[q * 3 + 2];

    const int idx = nbr[q * HN + lane];
    const float rx = s_pts[idx * 3 + 0] - qx;
    const float ry = s_pts[idx * 3 + 1] - qy;
    const float rz = s_pts[idx * 3 + 2] - qz;

    float wv[16];
    #pragma unroll
    for (int k = 0; k < 16; ++k) {
        float w = 0.f;
        if (k < KP) {
            float4 kv = kp4s[k];
            float dx = rx - kv.x, dy = ry - kv.y, dz = rz - kv.z;
            float d2 = fmaf(dx, dx, fmaf(dy, dy, dz * dz));
            float s  = fast_sqrt(d2);
            w = fmaxf(fmaf(s, -INV_E, 1.f), 0.f);
        }
        wv[k] = w;
    }
    ws4[warp][lane][0] = make_float4(wv[0],  wv[1],  wv[2],  wv[3]);
    ws4[warp][lane][1] = make_float4(wv[4],  wv[5],  wv[6],  wv[7]);
    ws4[warp][lane][2] = make_float4(wv[8],  wv[9],  wv[10], wv[11]);
    ws4[warp][lane][3] = make_float4(wv[12], wv[13], wv[14], wv[15]);
    __syncwarp();

    unsigned long long acc0[8], acc1[8];
    #pragma unroll
    for (int p = 0; p < 8; ++p) { acc0[p] = 0ULL; acc1[p] = 0ULL; }

    #pragma unroll 8
    for (int h = 0; h < HN; ++h) {
        const int ih = __shfl_sync(0xffffffffu, idx, h);
        const float2 xv = *(const float2*)(x + (size_t)ih * CIN + 2 * lane);
        const unsigned long long x0 = pk2(xv.x, xv.x);
        const unsigned long long x1 = pk2(xv.y, xv.y);
        const ulonglong2* wsv = (const ulonglong2*)&ws4[warp][h][0];
        #pragma unroll
        for (int pp = 0; pp < 4; ++pp) {
            ulonglong2 wp = wsv[pp];
            acc0[2 * pp]     = ffma2(wp.x, x0, acc0[2 * pp]);
            acc1[2 * pp]     = ffma2(wp.x, x1, acc1[2 * pp]);
            acc0[2 * pp + 1] = ffma2(wp.y, x0, acc0[2 * pp + 1]);
            acc1[2 * pp + 1] = ffma2(wp.y, x1, acc1[2 * pp + 1]);
        }
    }

    __nv_bfloat16* wh = g_wth + (size_t)q * KTOT + 2 * lane;
    __nv_bfloat16* wl = g_wtl + (size_t)q * KTOT + 2 * lane;
    #pragma unroll
    for (int p = 0; p < 8; ++p) {
        float v00, v10, v01, v11;
        upk2(acc0[p], v00, v10);
        upk2(acc1[p], v01, v11);
        {
            const int k = 2 * p;
            __nv_bfloat16 h0 = __float2bfloat16(v00);
            __nv_bfloat16 h1 = __float2bfloat16(v01);
            __nv_bfloat16 l0 = __float2bfloat16(v00 - __bfloat162float(h0));
            __nv_bfloat16 l1 = __float2bfloat16(v01 - __bfloat162float(h1));
            *(__nv_bfloat162*)(wh + k * 64) = __nv_bfloat162(h0, h1);
            *(__nv_bfloat162*)(wl + k * 64) = __nv_bfloat162(l0, l1);
        }
        if (2 * p + 1 < KP) {
            const int k = 2 * p + 1;
            __nv_bfloat16 h0 = __float2bfloat16(v10);
            __nv_bfloat16 h1 = __float2bfloat16(v11);
            __nv_bfloat16 l0 = __float2bfloat16(v10 - __bfloat162float(h0));
            __nv_bfloat16 l1 = __float2bfloat16(v11 - __bfloat162float(h1));
            *(__nv_bfloat162*)(wh + k * 64) = __nv_bfloat162(h0, h1);
            *(__nv_bfloat162*)(wl + k * 64) = __nv_bfloat162(l0, l1);
        }
    }
}

// =============================================================================
// Kernel B: HMMA GEMM, 32-wide k-chunks (SW64), 3 CTAs/SM target
//   out[128-tile][64] = weighted x W^T  (3-term bf16) + fused BN partials
// =============================================================================
// Per buffer: A_hi 8KB, A_lo 8KB, W_hi 4KB, W_lo 4KB = 24KB; x2 + red = 49664 B
#define HB_AH(b) ((b) * 24576u + 0u)
#define HB_AL(b) ((b) * 24576u + 8192u)
#define HB_WH(b) ((b) * 24576u + 16384u)
#define HB_WL(b) ((b) * 24576u + 20480u)
#define HB_RED   49152u
#define HB_TOTAL (49152 + 512)
#define NCHUNK   30                          // KTOT / 32

extern __shared__ char smH[];

static __device__ __forceinline__ void load_chunk32(uint32_t sb, int buf, int qbase, int c,
                                                    int tid) {
    // A hi/lo: 512 16B granules each (128 rows x 64B)
    #pragma unroll
    for (int i = 0; i < 2; ++i) {
        const int v = i * 256 + tid;
        const int row = v >> 2, u = v & 3;
        const uint32_t d = SWZ64((uint32_t)(row * 64 + u * 16));
        const size_t so = (size_t)(qbase + row) * KTOT + c * 32 + u * 8;
        cp_async16(sb + HB_AH(buf) + d, g_wth + so);
        cp_async16(sb + HB_AL(buf) + d, g_wtl + so);
    }
    // W hi/lo: 256 granules each (64 rows x 64B)
    {
        const int row = tid >> 2, u = tid & 3;
        const uint32_t d = SWZ64((uint32_t)(row * 64 + u * 16));
        const size_t so = (size_t)row * KTOT + c * 32 + u * 8;
        cp_async16(sb + HB_WH(buf) + d, g_Wth + so);
        cp_async16(sb + HB_WL(buf) + d, g_Wtl + so);
    }
    cp_commit();
}

__global__ void __launch_bounds__(256, 3)
kpconv_gemm_hmma(float* __restrict__ out)
{
    const uint32_t sb = smem_u32(smH);
    const int tid   = threadIdx.x;
    const int warp  = tid >> 5;
    const int lane  = tid & 31;
    const int qbase = blockIdx.x * 128;

    float* red  = (float*)(smH + HB_RED);
    float* red2 = red + 64;
    if (tid < 128) red[tid] = 0.f;

    const int a_row = warp * 16 + (lane & 15);
    const int a_cb  = (lane >> 4) * 16;
    const int b_row = (lane & 7) + ((lane >> 4) << 3);
    const int b_cb  = ((lane >> 3) & 1) * 16;

    float acc[8][4];
    #pragma unroll
    for (int t = 0; t < 8; ++t)
        #pragma unroll
        for (int e = 0; e < 4; ++e) acc[t][e] = 0.f;

    load_chunk32(sb, 0, qbase, 0, tid);
    load_chunk32(sb, 1, qbase, 1, tid);

    #pragma unroll 1
    for (int c = 0; c < NCHUNK; ++c) {
        const int buf = c & 1;
        if (c < NCHUNK - 1) cp_wait1(); else cp_wait0();
        __syncthreads();

        const uint32_t ahb = sb + HB_AH(buf);
        const uint32_t alb = sb + HB_AL(buf);
        const uint32_t whb = sb + HB_WH(buf);
        const uint32_t wlb = sb + HB_WL(buf);

        #pragma unroll
        for (int s = 0; s < 2; ++s) {
            const uint32_t aoff = SWZ64((uint32_t)(a_row * 64 + s * 32 + a_cb));
            uint32_t ah0, ah1, ah2, ah3, al0, al1, al2, al3;
            LDSM4(ah0, ah1, ah2, ah3, ahb + aoff);
            LDSM4(al0, al1, al2, al3, alb + aoff);

            #pragma unroll
            for (int p = 0; p < 4; ++p) {
                const uint32_t boff =
                    SWZ64((uint32_t)((p * 16 + b_row) * 64 + s * 32 + b_cb));
                uint32_t bh0, bh1, bh2, bh3, bl0, bl1, bl2, bl3;
                LDSM4(bh0, bh1, bh2, bh3, whb + boff);
                LDSM4(bl0, bl1, bl2, bl3, wlb + boff);

                MMA16816(acc[2 * p],     ah0, ah1, ah2, ah3, bh0, bh1);
                MMA16816(acc[2 * p],     ah0, ah1, ah2, ah3, bl0, bl1);
                MMA16816(acc[2 * p],     al0, al1, al2, al3, bh0, bh1);
                MMA16816(acc[2 * p + 1], ah0, ah1, ah2, ah3, bh2, bh3);
                MMA16816(acc[2 * p + 1], ah0, ah1, ah2, ah3, bl2, bl3);
                MMA16816(acc[2 * p + 1], al0, al1, al2, al3, bh2, bh3);
            }
        }

        __syncthreads();
        if (c + 2 < NCHUNK) load_chunk32(sb, buf, qbase, c + 2, tid);
    }

    // ---- epilogue: write + BN partials ----
    const int tm = lane >> 2;
    const int tn = (lane & 3) * 2;
    const int n0 = qbase + warp * 16 + tm;
    #pragma unroll
    for (int t = 0; t < 8; ++t) {
        const int col = t * 8 + tn;
        *(float2*)(out + (size_t)n0 * CO + col)       = make_float2(acc[t][0], acc[t][1]);
        *(float2*)(out + (size_t)(n0 + 8) * CO + col) = make_float2(acc[t][2], acc[t][3]);
        atomicAdd(red  + col,     acc[t][0] + acc[t][2]);
        atomicAdd(red  + col + 1, acc[t][1] + acc[t][3]);
        atomicAdd(red2 + col,     fmaf(acc[t][0], acc[t][0], acc[t][2] * acc[t][2]));
        atomicAdd(red2 + col + 1, fmaf(acc[t][1], acc[t][1], acc[t][3] * acc[t][3]));
    }
    __syncthreads();
    if (tid < 64)       atomicAdd(&g_sums[tid], red[tid]);
    else if (tid < 128) atomicAdd(&g_sumsq[tid - 64], red2[tid - 64]);
}

// =============================================================================
__global__ void finalize_stats_kernel(const float* __restrict__ gamma,
                                      const float* __restrict__ beta) {
    int o = threadIdx.x;
    if (o < CO) {
        const float invN = 1.f / (float)NQ;
        float mean = g_sums[o] * invN;
        float var  = g_sumsq[o] * invN - mean * mean;
        float inv  = rsqrtf(var + 1e-5f);
        float sc   = gamma[o] * inv;
        g_scale[o] = sc;
        g_bias[o]  = fmaf(-mean, sc, beta[o]);
    }
}

__global__ void __launch_bounds__(256)
bn_act_kernel(float* __restrict__ out) {
    const int i = blockIdx.x * 256 + threadIdx.x;
    float4 v = ((const float4*)out)[i];
    const int c = (i & 15) * 4;
    float r0 = fmaf(v.x, g_scale[c + 0], g_bias[c + 0]);
    float r1 = fmaf(v.y, g_scale[c + 1], g_bias[c + 1]);
    float r2 = fmaf(v.z, g_scale[c + 2], g_bias[c + 2]);
    float r3 = fmaf(v.w, g_scale[c + 3], g_bias[c + 3]);
    r0 = (r0 >= 0.f) ? r0 : 0.1f * r0;
    r1 = (r1 >= 0.f) ? r1 : 0.1f * r1;
    r2 = (r2 >= 0.f) ? r2 : 0.1f * r2;
    r3 = (r3 >= 0.f) ? r3 : 0.1f * r3;
    ((float4*)out)[i] = make_float4(r0, r1, r2, r3);
}

// =============================================================================
extern "C" void kernel_launch(void* const* d_in, const int* in_sizes, int n_in,
                              void* d_out, int out_size) {
    const float* x      = (const float*)d_in[0];
    const float* q_pts  = (const float*)d_in[1];
    const float* s_pts  = (const float*)d_in[2];
    const int*   nbr    = (const int*)d_in[3];
    const float* kp     = (const float*)d_in[4];
    const float* Wg     = (const float*)d_in[5];
    const float* gamma  = (const float*)d_in[6];
    const float* beta   = (const float*)d_in[7];
    float*       out    = (float*)d_out;

    cudaFuncSetAttribute(kpconv_gemm_hmma,
                         cudaFuncAttributeMaxDynamicSharedMemorySize, HB_TOTAL);

    prep_w<<<KTOT, 64>>>(Wg);
    kpconv_aggregate<<<NQ / 8, 256>>>(x, q_pts, s_pts, nbr, kp);
    kpconv_gemm_hmma<<<NQ / 128, 256, HB_TOTAL>>>(out);
    finalize_stats_kernel<<<1, 64>>>(gamma, beta);
    bn_act_kernel<<<(NQ * CO / 4) / 256, 256>>>(out);
}

// round 9
// speedup vs baseline: 1.3402x; 1.2136x over previous
#include <cuda_runtime.h>
#include <cuda_fp16.h>
#include <cstdint>
#include <cstddef>

#define NQ   65536
#define MS   65536
#define HN   32
#define CIN  64
#define CO   64
#define KP   15
#define KTOT 960            // KP * CIN

// ---- device scratch ----------------------------------------------------------
__device__ __half g_wt16[(size_t)NQ * KTOT];   // weighted, fp16
__device__ __half g_Wt16[(size_t)CO * KTOT];   // W^T [o][k*64+i], fp16

__device__ float g_sums[CO];
__device__ float g_sumsq[CO];
__device__ float g_scale[CO];
__device__ float g_bias[CO];

// ---- fp32x2 helpers ------------------------------------------------------------
static __device__ __forceinline__ unsigned long long pk2(float lo, float hi) {
    unsigned long long r;
    asm("mov.b64 %0, {%1, %2};" : "=l"(r) : "f"(lo), "f"(hi));
    return r;
}
static __device__ __forceinline__ void upk2(unsigned long long v, float &lo, float &hi) {
    asm("mov.b64 {%0, %1}, %2;" : "=f"(lo), "=f"(hi) : "l"(v));
}
static __device__ __forceinline__ unsigned long long ffma2(unsigned long long a,
                                                           unsigned long long b,
                                                           unsigned long long c) {
    unsigned long long d;
    asm("fma.rn.f32x2 %0, %1, %2, %3;" : "=l"(d) : "l"(a), "l"(b), "l"(c));
    return d;
}
static __device__ __forceinline__ float fast_sqrt(float x) {
    float r;
    asm("sqrt.approx.f32 %0, %1;" : "=f"(r) : "f"(x));
    return r;
}

// ---- cp.async -------------------------------------------------------------------
static __device__ __forceinline__ void cp_async16(uint32_t smem_dst, const void* gmem_src) {
    asm volatile("cp.async.cg.shared.global [%0], [%1], 16;"
                 :: "r"(smem_dst), "l"(gmem_src));
}
static __device__ __forceinline__ void cp_commit() { asm volatile("cp.async.commit_group;"); }
static __device__ __forceinline__ void cp_wait0()  { asm volatile("cp.async.wait_group 0;"); }
static __device__ __forceinline__ void cp_wait1()  { asm volatile("cp.async.wait_group 1;"); }

static __device__ __forceinline__ uint32_t smem_u32(const void* p) {
    uint32_t a;
    asm("{ .reg .u64 t; cvta.to.shared.u64 t, %1; cvt.u32.u64 %0, t; }" : "=r"(a) : "l"(p));
    return a;
}

#define SWZ128(b)   ((b) ^ (((b) >> 3) & 0x70))

#define LDSM4(r0, r1, r2, r3, addr) \
    asm volatile("ldmatrix.sync.aligned.m8n8.x4.shared.b16 {%0,%1,%2,%3}, [%4];" \
        : "=r"(r0), "=r"(r1), "=r"(r2), "=r"(r3) : "r"(addr))

#define MMA16816F(c, a0, a1, a2, a3, b0, b1) \
    asm volatile("mma.sync.aligned.m16n8k16.row.col.f32.f16.f16.f32 " \
        "{%0,%1,%2,%3}, {%4,%5,%6,%7}, {%8,%9}, {%0,%1,%2,%3};" \
        : "+f"((c)[0]), "+f"((c)[1]), "+f"((c)[2]), "+f"((c)[3]) \
        : "r"(a0), "r"(a1), "r"(a2), "r"(a3), "r"(b0), "r"(b1))

// =============================================================================
// Kernel P: transpose W -> Wt[o][k*64+i] fp16
// =============================================================================
__global__ void __launch_bounds__(64)
prep_w(const float* __restrict__ Wg) {
    const int ki = blockIdx.x;              // 0..959
    const int o  = threadIdx.x;             // 0..63
    g_Wt16[(size_t)o * KTOT + ki] = __float2half(Wg[ki * 64 + o]);
}

// =============================================================================
// Kernel A: FFMA2 aggregation (R5 structure — measured fastest)
//   warp per query; writes weighted fp16; block 0 zeroes BN accumulators
// =============================================================================
__global__ void __launch_bounds__(256)
kpconv_aggregate(const float* __restrict__ x,
                 const float* __restrict__ q_pts,
                 const float* __restrict__ s_pts,
                 const int*   __restrict__ nbr,
                 const float* __restrict__ kp)
{
    __shared__ float4 ws4[8][32][4];
    __shared__ float4 kp4s[16];

    const int tid  = threadIdx.x;
    const int warp = tid >> 5;
    const int lane = tid & 31;

    if (blockIdx.x == 0 && tid < CO) { g_sums[tid] = 0.f; g_sumsq[tid] = 0.f; }

    if (tid < 16) {
        float4 v = make_float4(0.f, 0.f, 0.f, 0.f);
        if (tid < KP) {
            v.x = kp[tid * 3 + 0];
            v.y = kp[tid * 3 + 1];
            v.z = kp[tid * 3 + 2];
        }
        kp4s[tid] = v;
    }
    __syncthreads();

    const double EXT_D = 0.1 * 1.2 / 2.5;
    const float  INV_E = (float)(1.0 / EXT_D);

    const int q = blockIdx.x * 8 + warp;

    const float qx = q_pts[q * 3 + 0];
    const float qy = q_pts[q * 3 + 1];
    const float qz = q_pts[q * 3 + 2];

    const int idx = nbr[q * HN + lane];
    const float rx = s_pts[idx * 3 + 0] - qx;
    const float ry = s_pts[idx * 3 + 1] - qy;
    const float rz = s_pts[idx * 3 + 2] - qz;

    float wv[16];
    #pragma unroll
    for (int k = 0; k < 16; ++k) {
        float w = 0.f;
        if (k < KP) {
            float4 kv = kp4s[k];
            float dx = rx - kv.x, dy = ry - kv.y, dz = rz - kv.z;
            float d2 = fmaf(dx, dx, fmaf(dy, dy, dz * dz));
            float s  = fast_sqrt(d2);
            w = fmaxf(fmaf(s, -INV_E, 1.f), 0.f);
        }
        wv[k] = w;
    }
    ws4[warp][lane][0] = make_float4(wv[0],  wv[1],  wv[2],  wv[3]);
    ws4[warp][lane][1] = make_float4(wv[4],  wv[5],  wv[6],  wv[7]);
    ws4[warp][lane][2] = make_float4(wv[8],  wv[9],  wv[10], wv[11]);
    ws4[warp][lane][3] = make_float4(wv[12], wv[13], wv[14], wv[15]);
    __syncwarp();

    unsigned long long acc0[8], acc1[8];
    #pragma unroll
    for (int p = 0; p < 8; ++p) { acc0[p] = 0ULL; acc1[p] = 0ULL; }

    #pragma unroll 8
    for (int h = 0; h < HN; ++h) {
        const int ih = __shfl_sync(0xffffffffu, idx, h);
        const float2 xv = *(const float2*)(x + (size_t)ih * CIN + 2 * lane);
        const unsigned long long x0 = pk2(xv.x, xv.x);
        const unsigned long long x1 = pk2(xv.y, xv.y);
        const ulonglong2* wsv = (const ulonglong2*)&ws4[warp][h][0];
        #pragma unroll
        for (int pp = 0; pp < 4; ++pp) {
            ulonglong2 wp = wsv[pp];
            acc0[2 * pp]     = ffma2(wp.x, x0, acc0[2 * pp]);
            acc1[2 * pp]     = ffma2(wp.x, x1, acc1[2 * pp]);
            acc0[2 * pp + 1] = ffma2(wp.y, x0, acc0[2 * pp + 1]);
            acc1[2 * pp + 1] = ffma2(wp.y, x1, acc1[2 * pp + 1]);
        }
    }

    // store weighted as fp16 (coalesced 128B per k per warp)
    __half* wd = g_wt16 + (size_t)q * KTOT + 2 * lane;
    #pragma unroll
    for (int p = 0; p < 8; ++p) {
        float v00, v10, v01, v11;
        upk2(acc0[p], v00, v10);   // {k=2p ch0, k=2p+1 ch0}
        upk2(acc1[p], v01, v11);   // {k=2p ch1, k=2p+1 ch1}
        *(__half2*)(wd + (2 * p) * 64) = __floats2half2_rn(v00, v01);
        if (2 * p + 1 < KP)
            *(__half2*)(wd + (2 * p + 1) * 64) = __floats2half2_rn(v10, v11);
    }
}

// =============================================================================
// Kernel B: HMMA GEMM (single fp16 term), 64-wide k-chunks, SW128
//   out[128-tile][64] = weighted x W^T + fused BN partial sums
//   SMEM: 2 x (A 16KB + W 8KB) + red 512B = 49664 B  -> 3 CTAs/SM
// =============================================================================
#define HB_A(b)  ((b) * 24576u)
#define HB_W(b)  ((b) * 24576u + 16384u)
#define HB_RED   49152u
#define HB_TOTAL (49152 + 512)

extern __shared__ char smH[];

static __device__ __forceinline__ void load_chunk(uint32_t sb, int buf, int qbase, int c,
                                                  int tid) {
    // A: 1024 16B granules (128 rows x 128B)
    #pragma unroll
    for (int i = 0; i < 4; ++i) {
        const int v = i * 256 + tid;
        const int row = v >> 3, u = v & 7;
        const uint32_t d = SWZ128((uint32_t)(row * 128 + u * 16));
        cp_async16(sb + HB_A(buf) + d, g_wt16 + (size_t)(qbase + row) * KTOT + c * 64 + u * 8);
    }
    // W: 512 granules (64 rows x 128B)
    #pragma unroll
    for (int i = 0; i < 2; ++i) {
        const int v = i * 256 + tid;
        const int row = v >> 3, u = v & 7;
        const uint32_t d = SWZ128((uint32_t)(row * 128 + u * 16));
        cp_async16(sb + HB_W(buf) + d, g_Wt16 + (size_t)row * KTOT + c * 64 + u * 8);
    }
    cp_commit();
}

__global__ void __launch_bounds__(256, 3)
kpconv_gemm_hmma(float* __restrict__ out)
{
    const uint32_t sb = smem_u32(smH);
    const int tid   = threadIdx.x;
    const int warp  = tid >> 5;
    const int lane  = tid & 31;
    const int qbase = blockIdx.x * 128;

    float* red  = (float*)(smH + HB_RED);
    float* red2 = red + 64;
    if (tid < 128) red[tid] = 0.f;

    const int a_row = warp * 16 + (lane & 15);
    const int a_cb  = (lane >> 4) * 16;
    const int b_row = (lane & 7) + ((lane >> 4) << 3);
    const int b_cb  = ((lane >> 3) & 1) * 16;

    float acc[8][4];
    #pragma unroll
    for (int t = 0; t < 8; ++t)
        #pragma unroll
        for (int e = 0; e < 4; ++e) acc[t][e] = 0.f;

    load_chunk(sb, 0, qbase, 0, tid);
    load_chunk(sb, 1, qbase, 1, tid);

    #pragma unroll 1
    for (int c = 0; c < 15; ++c) {
        const int buf = c & 1;
        if (c < 14) cp_wait1(); else cp_wait0();
        __syncthreads();

        const uint32_t ab = sb + HB_A(buf);
        const uint32_t wb = sb + HB_W(buf);

        #pragma unroll
        for (int s = 0; s < 4; ++s) {
            const uint32_t aoff = SWZ128((uint32_t)(a_row * 128 + s * 32 + a_cb));
            uint32_t a0, a1, a2, a3;
            LDSM4(a0, a1, a2, a3, ab + aoff);

            #pragma unroll
            for (int p = 0; p < 4; ++p) {
                const uint32_t boff =
                    SWZ128((uint32_t)((p * 16 + b_row) * 128 + s * 32 + b_cb));
                uint32_t b0, b1, b2, b3;
                LDSM4(b0, b1, b2, b3, wb + boff);
                MMA16816F(acc[2 * p],     a0, a1, a2, a3, b0, b1);
                MMA16816F(acc[2 * p + 1], a0, a1, a2, a3, b2, b3);
            }
        }

        __syncthreads();
        if (c + 2 < 15) load_chunk(sb, buf, qbase, c + 2, tid);
    }

    // ---- epilogue: write + BN partials ----
    const int tm = lane >> 2;
    const int tn = (lane & 3) * 2;
    const int n0 = qbase + warp * 16 + tm;
    #pragma unroll
    for (int t = 0; t < 8; ++t) {
        const int col = t * 8 + tn;
        *(float2*)(out + (size_t)n0 * CO + col)       = make_float2(acc[t][0], acc[t][1]);
        *(float2*)(out + (size_t)(n0 + 8) * CO + col) = make_float2(acc[t][2], acc[t][3]);
        atomicAdd(red  + col,     acc[t][0] + acc[t][2]);
        atomicAdd(red  + col + 1, acc[t][1] + acc[t][3]);
        atomicAdd(red2 + col,     fmaf(acc[t][0], acc[t][0], acc[t][2] * acc[t][2]));
        atomicAdd(red2 + col + 1, fmaf(acc[t][1], acc[t][1], acc[t][3] * acc[t][3]));
    }
    __syncthreads();
    if (tid < 64)       atomicAdd(&g_sums[tid], red[tid]);
    else if (tid < 128) atomicAdd(&g_sumsq[tid - 64], red2[tid - 64]);
}

// =============================================================================
__global__ void finalize_stats_kernel(const float* __restrict__ gamma,
                                      const float* __restrict__ beta) {
    int o = threadIdx.x;
    if (o < CO) {
        const float invN = 1.f / (float)NQ;
        float mean = g_sums[o] * invN;
        float var  = g_sumsq[o] * invN - mean * mean;
        float inv  = rsqrtf(var + 1e-5f);
        float sc   = gamma[o] * inv;
        g_scale[o] = sc;
        g_bias[o]  = fmaf(-mean, sc, beta[o]);
    }
}

__global__ void __launch_bounds__(256)
bn_act_kernel(float* __restrict__ out) {
    const int i = blockIdx.x * 256 + threadIdx.x;
    float4 v = ((const float4*)out)[i];
    const int c = (i & 15) * 4;
    float r0 = fmaf(v.x, g_scale[c + 0], g_bias[c + 0]);
    float r1 = fmaf(v.y, g_scale[c + 1], g_bias[c + 1]);
    float r2 = fmaf(v.z, g_scale[c + 2], g_bias[c + 2]);
    float r3 = fmaf(v.w, g_scale[c + 3], g_bias[c + 3]);
    r0 = (r0 >= 0.f) ? r0 : 0.1f * r0;
    r1 = (r1 >= 0.f) ? r1 : 0.1f * r1;
    r2 = (r2 >= 0.f) ? r2 : 0.1f * r2;
    r3 = (r3 >= 0.f) ? r3 : 0.1f * r3;
    ((float4*)out)[i] = make_float4(r0, r1, r2, r3);
}

// =============================================================================
extern "C" void kernel_launch(void* const* d_in, const int* in_sizes, int n_in,
                              void* d_out, int out_size) {
    const float* x      = (const float*)d_in[0];
    const float* q_pts  = (const float*)d_in[1];
    const float* s_pts  = (const float*)d_in[2];
    const int*   nbr    = (const int*)d_in[3];
    const float* kp     = (const float*)d_in[4];
    const float* Wg     = (const float*)d_in[5];
    const float* gamma  = (const float*)d_in[6];
    const float* beta   = (const float*)d_in[7];
    float*       out    = (float*)d_out;

    cudaFuncSetAttribute(kpconv_gemm_hmma,
                         cudaFuncAttributeMaxDynamicSharedMemorySize, HB_TOTAL);

    prep_w<<<KTOT, 64>>>(Wg);
    kpconv_aggregate<<<NQ / 8, 256>>>(x, q_pts, s_pts, nbr, kp);
    kpconv_gemm_hmma<<<NQ / 128, 256, HB_TOTAL>>>(out);
    finalize_stats_kernel<<<1, 64>>>(gamma, beta);
    bn_act_kernel<<<(NQ * CO / 4) / 256, 256>>>(out);
}

// round 10
// speedup vs baseline: 1.5283x; 1.1404x over previous
#include <cuda_runtime.h>
#include <cuda_fp16.h>
#include <cstdint>
#include <cstddef>

#define NQ   65536
#define MS   65536
#define HN   32
#define CIN  64
#define CO   64
#define KP   15
#define KTOT 960            // KP * CIN

// ---- device scratch ----------------------------------------------------------
__device__ __half g_wt16[(size_t)NQ * KTOT];   // weighted, fp16
__device__ __half g_Wt16[(size_t)CO * KTOT];   // W^T [o][k*64+i], fp16
__device__ __half g_x16[(size_t)MS * CIN];     // x, fp16

__device__ float g_sums[CO];
__device__ float g_sumsq[CO];

// ---- helpers -------------------------------------------------------------------
static __device__ __forceinline__ float fast_sqrt(float x) {
    float r;
    asm("sqrt.approx.f32 %0, %1;" : "=f"(r) : "f"(x));
    return r;
}
static __device__ __forceinline__ void cp_async16(uint32_t smem_dst, const void* gmem_src) {
    asm volatile("cp.async.cg.shared.global [%0], [%1], 16;"
                 :: "r"(smem_dst), "l"(gmem_src));
}
static __device__ __forceinline__ void cp_commit() { asm volatile("cp.async.commit_group;"); }
static __device__ __forceinline__ void cp_wait0()  { asm volatile("cp.async.wait_group 0;"); }
static __device__ __forceinline__ void cp_wait1()  { asm volatile("cp.async.wait_group 1;"); }
static __device__ __forceinline__ void cp_wait2()  { asm volatile("cp.async.wait_group 2;"); }

static __device__ __forceinline__ uint32_t smem_u32(const void* p) {
    uint32_t a;
    asm("{ .reg .u64 t; cvta.to.shared.u64 t, %1; cvt.u32.u64 %0, t; }" : "=r"(a) : "l"(p));
    return a;
}

#define SWZ128(b)   ((b) ^ (((b) >> 3) & 0x70))

#define LDSM4(r0, r1, r2, r3, addr) \
    asm volatile("ldmatrix.sync.aligned.m8n8.x4.shared.b16 {%0,%1,%2,%3}, [%4];" \
        : "=r"(r0), "=r"(r1), "=r"(r2), "=r"(r3) : "r"(addr))

#define LDSM4T(r0, r1, r2, r3, addr) \
    asm volatile("ldmatrix.sync.aligned.m8n8.x4.trans.shared.b16 {%0,%1,%2,%3}, [%4];" \
        : "=r"(r0), "=r"(r1), "=r"(r2), "=r"(r3) : "r"(addr))

#define MMA16816F(c, a0, a1, a2, a3, b0, b1) \
    asm volatile("mma.sync.aligned.m16n8k16.row.col.f32.f16.f16.f32 " \
        "{%0,%1,%2,%3}, {%4,%5,%6,%7}, {%8,%9}, {%0,%1,%2,%3};" \
        : "+f"((c)[0]), "+f"((c)[1]), "+f"((c)[2]), "+f"((c)[3]) \
        : "r"(a0), "r"(a1), "r"(a2), "r"(a3), "r"(b0), "r"(b1))

// =============================================================================
// Kernel P1: x -> fp16
// =============================================================================
__global__ void __launch_bounds__(256)
prep_x16(const float* __restrict__ x) {
    const int i = blockIdx.x * 256 + threadIdx.x;
    g_x16[i] = __float2half(x[i]);
}

// =============================================================================
// Kernel P2: transpose W -> Wt[o][k*64+i] fp16
// =============================================================================
__global__ void __launch_bounds__(64)
prep_w(const float* __restrict__ Wg) {
    const int ki = blockIdx.x;              // 0..959
    const int o  = threadIdx.x;             // 0..63
    g_Wt16[(size_t)o * KTOT + ki] = __float2half(Wg[ki * 64 + o]);
}

// =============================================================================
// Kernel A: HMMA aggregation, warp-pipelined, 20 warps/SM.
//   Per query: weighted[16(pad),64] = (infl_hi + infl_lo)[16,32] x x16[32,64]
//   Per-warp smem: x dbl-buf 2x4KB (SW128 128B rows) + infl hi/lo 2x1280B (80B rows)
// =============================================================================
#define QW       8
#define AGW      10752u                     // per-warp smem bytes
#define AG_XB(b) ((b) * 4096u)
#define AG_IH    8192u
#define AG_IL    9472u
#define AGG_SMEM (4 * AGW)                  // 43008 bytes (128-thr CTA, 4 warps)

__global__ void __launch_bounds__(128)
kpconv_aggregate_tc(const float* __restrict__ q_pts,
                    const float* __restrict__ s_pts,
                    const int*   __restrict__ nbr,
                    const float* __restrict__ kp)
{
    extern __shared__ char smA[];
    __shared__ float4 kp4s[16];

    const int tid  = threadIdx.x;
    const int warp = tid >> 5;
    const int lane = tid & 31;
    const uint32_t wb = smem_u32(smA) + warp * AGW;

    if (blockIdx.x == 0 && tid < CO) { g_sums[tid] = 0.f; g_sumsq[tid] = 0.f; }

    if (tid < 16) {
        float4 v = make_float4(0.f, 0.f, 0.f, 0.f);
        if (tid < KP) {
            v.x = kp[tid * 3 + 0];
            v.y = kp[tid * 3 + 1];
            v.z = kp[tid * 3 + 2];
        }
        kp4s[tid] = v;
    }
    __syncthreads();

    const double EXT_D = 0.1 * 1.2 / 2.5;
    const float  INV_E = (float)(1.0 / EXT_D);

    const int q0 = (blockIdx.x * 4 + warp) * QW;

    // validated fragment mappings (R6)
    const int krow_base  = (lane & 7) + ((lane >> 3) & 1) * 8;
    const uint32_t a_off = (uint32_t)((lane & 15) * 80 + (lane >> 4) * 16);
    const int kp0 = lane >> 2;
    const int kp1 = kp0 + 8;
    const int cb  = 2 * (lane & 3);

    // ---- prologue: gather x for q0 into buffer 0 ----
    int idx_cur = nbr[q0 * HN + lane];
    #pragma unroll
    for (int i = 0; i < 8; ++i) {
        const int v = i * 32 + lane;
        const int r = v >> 3, u = v & 7;
        const int ir = __shfl_sync(0xffffffffu, idx_cur, r);
        cp_async16(wb + AG_XB(0) + SWZ128((uint32_t)(r * 128 + u * 16)),
                   g_x16 + (size_t)ir * CIN + u * 8);
    }
    cp_commit();

    #pragma unroll 1
    for (int qi = 0; qi < QW; ++qi) {
        const int q = q0 + qi;

        // ---- issue gather for q+1 ----
        int idx_next = 0;
        if (qi + 1 < QW) {
            idx_next = nbr[(q + 1) * HN + lane];
            const uint32_t xb = wb + AG_XB((qi + 1) & 1);
            #pragma unroll
            for (int i = 0; i < 8; ++i) {
                const int v = i * 32 + lane;
                const int r = v >> 3, u = v & 7;
                const int ir = __shfl_sync(0xffffffffu, idx_next, r);
                cp_async16(xb + SWZ128((uint32_t)(r * 128 + u * 16)),
                           g_x16 + (size_t)ir * CIN + u * 8);
            }
            cp_commit();
        }

        // ---- influence for q (lane = neighbor), fp16 hi/lo ----
        const float qx = q_pts[q * 3 + 0];
        const float qy = q_pts[q * 3 + 1];
        const float qz = q_pts[q * 3 + 2];
        const float rx = s_pts[idx_cur * 3 + 0] - qx;
        const float ry = s_pts[idx_cur * 3 + 1] - qy;
        const float rz = s_pts[idx_cur * 3 + 2] - qz;

        #pragma unroll
        for (int k = 0; k < 16; ++k) {
            float w = 0.f;
            if (k < KP) {
                float4 kv = kp4s[k];
                float dx = rx - kv.x, dy = ry - kv.y, dz = rz - kv.z;
                float d2 = fmaf(dx, dx, fmaf(dy, dy, dz * dz));
                float s  = fast_sqrt(d2);
                w = fmaxf(fmaf(s, -INV_E, 1.f), 0.f);
            }
            __half h = __float2half(w);
            __half l = __float2half(w - __half2float(h));
            asm volatile("st.shared.b16 [%0], %1;"
                         :: "r"(wb + AG_IH + k * 80 + lane * 2),
                            "h"(*(unsigned short*)&h) : "memory");
            asm volatile("st.shared.b16 [%0], %1;"
                         :: "r"(wb + AG_IL + k * 80 + lane * 2),
                            "h"(*(unsigned short*)&l) : "memory");
        }
        __syncwarp();

        // ---- wait for q's gather ----
        if (qi + 1 < QW) cp_wait1(); else cp_wait0();
        __syncwarp();

        const uint32_t xb = wb + AG_XB(qi & 1);

        float acc[8][4];
        #pragma unroll
        for (int t = 0; t < 8; ++t)
            #pragma unroll
            for (int e = 0; e < 4; ++e) acc[t][e] = 0.f;

        #pragma unroll
        for (int s = 0; s < 2; ++s) {
            uint32_t ah0, ah1, ah2, ah3, al0, al1, al2, al3;
            LDSM4(ah0, ah1, ah2, ah3, wb + AG_IH + a_off + s * 32);
            LDSM4(al0, al1, al2, al3, wb + AG_IL + a_off + s * 32);

            const int krow = s * 16 + krow_base;
            #pragma unroll
            for (int t = 0; t < 4; ++t) {
                const uint32_t boff =
                    SWZ128((uint32_t)(krow * 128 + t * 32 + ((lane >> 4) * 16)));
                uint32_t b0, b1, b2, b3;
                LDSM4T(b0, b1, b2, b3, xb + boff);

                MMA16816F(acc[2 * t],     ah0, ah1, ah2, ah3, b0, b1);
                MMA16816F(acc[2 * t],     al0, al1, al2, al3, b0, b1);
                MMA16816F(acc[2 * t + 1], ah0, ah1, ah2, ah3, b2, b3);
                MMA16816F(acc[2 * t + 1], al0, al1, al2, al3, b2, b3);
            }
        }
        __syncwarp();

        // ---- epilogue: weighted -> fp16 ----
        __half* dst = g_wt16 + (size_t)q * KTOT;
        #pragma unroll
        for (int t = 0; t < 8; ++t) {
            const int c = t * 8 + cb;
            *(__half2*)(dst + kp0 * 64 + c) = __floats2half2_rn(acc[t][0], acc[t][1]);
            if (kp1 < KP)
                *(__half2*)(dst + kp1 * 64 + c) = __floats2half2_rn(acc[t][2], acc[t][3]);
        }

        idx_cur = idx_next;
    }
}

// =============================================================================
// Kernel B: HMMA GEMM (single fp16 term), 64-wide k-chunks, 3-stage pipeline
//   out[128-tile][64] = weighted x W^T + fused BN partial sums
//   SMEM: 3 x (A 16KB + W 8KB) + red 512B = 74240 B -> 3 CTAs/SM
// =============================================================================
#define HB_A(b)  ((b) * 24576u)
#define HB_W(b)  ((b) * 24576u + 16384u)
#define HB_RED   73728u
#define HB_TOTAL (73728 + 512)

extern __shared__ char smH[];

static __device__ __forceinline__ void load_chunk(uint32_t sb, int buf, int qbase, int c,
                                                  int tid) {
    #pragma unroll
    for (int i = 0; i < 4; ++i) {
        const int v = i * 256 + tid;
        const int row = v >> 3, u = v & 7;
        const uint32_t d = SWZ128((uint32_t)(row * 128 + u * 16));
        cp_async16(sb + HB_A(buf) + d, g_wt16 + (size_t)(qbase + row) * KTOT + c * 64 + u * 8);
    }
    #pragma unroll
    for (int i = 0; i < 2; ++i) {
        const int v = i * 256 + tid;
        const int row = v >> 3, u = v & 7;
        const uint32_t d = SWZ128((uint32_t)(row * 128 + u * 16));
        cp_async16(sb + HB_W(buf) + d, g_Wt16 + (size_t)row * KTOT + c * 64 + u * 8);
    }
    cp_commit();
}

__global__ void __launch_bounds__(256, 3)
kpconv_gemm_hmma(float* __restrict__ out)
{
    const uint32_t sb = smem_u32(smH);
    const int tid   = threadIdx.x;
    const int warp  = tid >> 5;
    const int lane  = tid & 31;
    const int qbase = blockIdx.x * 128;

    float* red  = (float*)(smH + HB_RED);
    float* red2 = red + 64;
    if (tid < 128) red[tid] = 0.f;

    const int a_row = warp * 16 + (lane & 15);
    const int a_cb  = (lane >> 4) * 16;
    const int b_row = (lane & 7) + ((lane >> 4) << 3);
    const int b_cb  = ((lane >> 3) & 1) * 16;

    float acc[8][4];
    #pragma unroll
    for (int t = 0; t < 8; ++t)
        #pragma unroll
        for (int e = 0; e < 4; ++e) acc[t][e] = 0.f;

    load_chunk(sb, 0, qbase, 0, tid);
    load_chunk(sb, 1, qbase, 1, tid);
    load_chunk(sb, 2, qbase, 2, tid);

    int buf = 0;
    #pragma unroll 1
    for (int c = 0; c < 15; ++c) {
        if (c <= 12)      cp_wait2();
        else if (c == 13) cp_wait1();
        else              cp_wait0();
        __syncthreads();

        const uint32_t ab = sb + HB_A(buf);
        const uint32_t wbm = sb + HB_W(buf);

        #pragma unroll
        for (int s = 0; s < 4; ++s) {
            const uint32_t aoff = SWZ128((uint32_t)(a_row * 128 + s * 32 + a_cb));
            uint32_t a0, a1, a2, a3;
            LDSM4(a0, a1, a2, a3, ab + aoff);

            #pragma unroll
            for (int p = 0; p < 4; ++p) {
                const uint32_t boff =
                    SWZ128((uint32_t)((p * 16 + b_row) * 128 + s * 32 + b_cb));
                uint32_t b0, b1, b2, b3;
                LDSM4(b0, b1, b2, b3, wbm + boff);
                MMA16816F(acc[2 * p],     a0, a1, a2, a3, b0, b1);
                MMA16816F(acc[2 * p + 1], a0, a1, a2, a3, b2, b3);
            }
        }

        __syncthreads();
        if (c + 3 < 15) load_chunk(sb, buf, qbase, c + 3, tid);
        buf = (buf == 2) ? 0 : buf + 1;
    }

    // ---- epilogue: write + BN partials ----
    const int tm = lane >> 2;
    const int tn = (lane & 3) * 2;
    const int n0 = qbase + warp * 16 + tm;
    #pragma unroll
    for (int t = 0; t < 8; ++t) {
        const int col = t * 8 + tn;
        *(float2*)(out + (size_t)n0 * CO + col)       = make_float2(acc[t][0], acc[t][1]);
        *(float2*)(out + (size_t)(n0 + 8) * CO + col) = make_float2(acc[t][2], acc[t][3]);
        atomicAdd(red  + col,     acc[t][0] + acc[t][2]);
        atomicAdd(red  + col + 1, acc[t][1] + acc[t][3]);
        atomicAdd(red2 + col,     fmaf(acc[t][0], acc[t][0], acc[t][2] * acc[t][2]));
        atomicAdd(red2 + col + 1, fmaf(acc[t][1], acc[t][1], acc[t][3] * acc[t][3]));
    }
    __syncthreads();
    if (tid < 64)       atomicAdd(&g_sums[tid], red[tid]);
    else if (tid < 128) atomicAdd(&g_sumsq[tid - 64], red2[tid - 64]);
}

// =============================================================================
// Kernel: BN finalize (per-block, redundant) + apply + LeakyReLU(0.1)
// =============================================================================
__global__ void __launch_bounds__(256)
bn_act_kernel(float* __restrict__ out,
              const float* __restrict__ gamma,
              const float* __restrict__ beta) {
    __shared__ float sc[64], sbf[64];
    if (threadIdx.x < 64) {
        const int o = threadIdx.x;
        const float invN = 1.f / (float)NQ;
        float mean = g_sums[o] * invN;
        float var  = g_sumsq[o] * invN - mean * mean;
        float inv  = rsqrtf(var + 1e-5f);
        float s    = gamma[o] * inv;
        sc[o]  = s;
        sbf[o] = fmaf(-mean, s, beta[o]);
    }
    __syncthreads();

    const int i = blockIdx.x * 256 + threadIdx.x;
    float4 v = ((const float4*)out)[i];
    const int c = (i & 15) * 4;
    float r0 = fmaf(v.x, sc[c + 0], sbf[c + 0]);
    float r1 = fmaf(v.y, sc[c + 1], sbf[c + 1]);
    float r2 = fmaf(v.z, sc[c + 2], sbf[c + 2]);
    float r3 = fmaf(v.w, sc[c + 3], sbf[c + 3]);
    r0 = (r0 >= 0.f) ? r0 : 0.1f * r0;
    r1 = (r1 >= 0.f) ? r1 : 0.1f * r1;
    r2 = (r2 >= 0.f) ? r2 : 0.1f * r2;
    r3 = (r3 >= 0.f) ? r3 : 0.1f * r3;
    ((float4*)out)[i] = make_float4(r0, r1, r2, r3);
}

// =============================================================================
extern "C" void kernel_launch(void* const* d_in, const int* in_sizes, int n_in,
                              void* d_out, int out_size) {
    const float* x      = (const float*)d_in[0];
    const float* q_pts  = (const float*)d_in[1];
    const float* s_pts  = (const float*)d_in[2];
    const int*   nbr    = (const int*)d_in[3];
    const float* kp     = (const float*)d_in[4];
    const float* Wg     = (const float*)d_in[5];
    const float* gamma  = (const float*)d_in[6];
    const float* beta   = (const float*)d_in[7];
    float*       out    = (float*)d_out;

    cudaFuncSetAttribute(kpconv_gemm_hmma,
                         cudaFuncAttributeMaxDynamicSharedMemorySize, HB_TOTAL);

    prep_x16<<<(MS * CIN) / 256, 256>>>(x);
    prep_w<<<KTOT, 64>>>(Wg);
    kpconv_aggregate_tc<<<NQ / (4 * QW), 128, AGG_SMEM>>>(q_pts, s_pts, nbr, kp);
    kpconv_gemm_hmma<<<NQ / 128, 256, HB_TOTAL>>>(out);
    bn_act_kernel<<<(NQ * CO / 4) / 256, 256>>>(out, gamma, beta);
}